// round 8
// baseline (speedup 1.0000x reference)
#include <cuda_runtime.h>
#include <cstdint>

// Problem shape (fixed by the dataset instance)
#define NBATCH 32
#define EDIM   512
#define TDIM   512
#define M_ROWS 16384           // NBATCH*TDIM
#define NE     8192            // number of codes
#define NET    8388608         // NBATCH*EDIM*TDIM

// ---- scratch (__device__ globals; no allocations allowed) ----
__device__ float  g_zz[M_ROWS];
__device__ float  g_see[NE];
__device__ float  g_pval[2 * M_ROWS];
__device__ int    g_pidx[2 * M_ROWS];
__device__ int    g_idx[M_ROWS];
__device__ int    g_counts[NE];
__device__ double g_loss;

// ============================================================
// Row sum-of-squares (zz / see). zz shifts every d_j of a row
// uniformly (argmin-invariant) and see perturbations are ~6e-11
// vs the 6.1e-5 d-bucket -> neither needs bitwise matching.
// ============================================================
__device__ __forceinline__ float row_sumsq(float x0, float x1,
                                           float* ws, int tid) {
    float v = __fadd_rn(__fmul_rn(x0, x0), __fmul_rn(x1, x1));
    #pragma unroll
    for (int o = 16; o >= 1; o >>= 1)
        v = __fadd_rn(v, __shfl_down_sync(0xffffffffu, v, o));
    if ((tid & 31) == 0) ws[tid >> 5] = v;
    __syncthreads();
    float r = 0.f;
    if (tid < 32) {
        float p = (tid < 8) ? ws[tid] : 0.f;
        #pragma unroll
        for (int o = 16; o >= 1; o >>= 1)
            p = __fadd_rn(p, __shfl_down_sync(0xffffffffu, p, o));
        r = p;
    }
    return r;
}

__global__ void see_kernel(const float* __restrict__ emb) {
    __shared__ float ws[8];
    const int j = blockIdx.x, tid = threadIdx.x;
    float2 x = *(const float2*)(emb + (size_t)j * EDIM + 2 * tid);
    float r = row_sumsq(x.x, x.y, ws, tid);
    if (tid == 0) {
        g_see[j]    = r;
        g_counts[j] = 0;
        if (j == 0) g_loss = 0.0;
    }
}

// zz row m = (n,t): logical zf row, physical stride TDIM in z
__global__ void zz_kernel(const float* __restrict__ z) {
    __shared__ float ws[8];
    const int m = blockIdx.x, tid = threadIdx.x;
    const int n = m >> 9, t = m & 511;
    const float* base = z + (size_t)n * (EDIM * TDIM) + t;
    float x0 = base[(size_t)(2 * tid)     * TDIM];
    float x1 = base[(size_t)(2 * tid + 1) * TDIM];
    float r = row_sumsq(x0, x1, ws, tid);
    if (tid == 0) g_zz[m] = r;
}

// ============================================================
// Kernel 2: FULL-FP32 GEMM (g = zf . e_j): serial FFMA chain,
// K strictly ascending, ONE accumulator per element — the same
// per-element accumulation cuBLAS SGEMM threads perform.
// Epilogue = the reference's exact fp32 expression tree:
//   d = fl( fl(zz + see) - fl(g + g) )      (g+g exact)
// which reproduces the coarse d-bucketing (ulp ~6.1e-5 at |d|~512)
// that creates the ties argmin resolves by lowest index.
// 128x128x16 tiles, 8x8 microtile, 256 threads, 2 blocks/SM.
// grid = (2 code halves, 128 row tiles)
// ============================================================
#define BM 128
#define BN 128
#define BK 16
#define NTILES_J 32   // 4096 codes per half / 128
#define NCHUNK_K 32   // 512 / 16

__global__ __launch_bounds__(256, 2)
void vq_argmin_kernel(const float* __restrict__ z,
                      const float* __restrict__ emb) {
    __shared__ float As[BK][BM];   // [k][m]
    __shared__ float Bs[BK][BN];   // [k][j]

    const int tid = threadIdx.x;
    const int h   = blockIdx.x;          // code half 0/1
    const int rt  = blockIdx.y;          // row tile 0..127
    const int m0  = rt * BM;
    const int n   = m0 >> 9;
    const int t0  = m0 & 511;
    const float* zbase = z + ((size_t)n * EDIM * TDIM) + t0;

    const int warpId = tid >> 5, lane = tid & 31;
    const int wy = warpId >> 1, wx = warpId & 1;
    const int wr = lane >> 3,   wc = lane & 7;
    const int rowb = wy * 32 + wr * 8;   // first local row
    const int colb = wx * 64 + wc * 8;   // first local code

    // zz for this thread's 8 rows (row shift is argmin-neutral but the
    // BUCKETING of fl(zz+see)-2g is not -> must include it in d)
    float zzr[8];
    #pragma unroll
    for (int i = 0; i < 8; i++) zzr[i] = __ldg(&g_zz[m0 + rowb + i]);

    float bestv[8];
    int   besti[8];
    #pragma unroll
    for (int i = 0; i < 8; i++) { bestv[i] = 3.4e38f; besti[i] = 0x7fffffff; }

    const int jhalf0 = h * (NE / 2);

    for (int jt = 0; jt < NTILES_J; ++jt) {
        const int j0 = jhalf0 + jt * BN;
        float acc[8][8];
        #pragma unroll
        for (int i = 0; i < 8; i++)
            #pragma unroll
            for (int c = 0; c < 8; c++) acc[i][c] = 0.f;

        for (int kt = 0; kt < NCHUNK_K; ++kt) {     // K ascending
            const int e0 = kt * BK;
            // z chunk: 16 k-rows x 128 contiguous floats (coalesced f4)
            #pragma unroll
            for (int it = 0; it < 2; ++it) {
                int id = tid + it * 256;
                int k  = id >> 5;
                int f4 = id & 31;
                float4 v = *(const float4*)(zbase + (size_t)(e0 + k) * TDIM + f4 * 4);
                *(float4*)(&As[k][f4 * 4]) = v;
            }
            // emb chunk: 128 code rows x 16 e's, transpose into [k][j]
            #pragma unroll
            for (int it = 0; it < 2; ++it) {
                int id = tid + it * 256;
                int j  = id >> 2;
                int k4 = id & 3;
                float4 v = *(const float4*)(emb + (size_t)(j0 + j) * EDIM + e0 + k4 * 4);
                Bs[k4 * 4 + 0][j] = v.x;
                Bs[k4 * 4 + 1][j] = v.y;
                Bs[k4 * 4 + 2][j] = v.z;
                Bs[k4 * 4 + 3][j] = v.w;
            }
            __syncthreads();
            #pragma unroll
            for (int kk = 0; kk < BK; ++kk) {       // serial FFMA chain
                float a[8], b[8];
                *(float4*)&a[0] = *(const float4*)&As[kk][rowb];
                *(float4*)&a[4] = *(const float4*)&As[kk][rowb + 4];
                *(float4*)&b[0] = *(const float4*)&Bs[kk][colb];
                *(float4*)&b[4] = *(const float4*)&Bs[kk][colb + 4];
                #pragma unroll
                for (int i = 0; i < 8; i++)
                    #pragma unroll
                    for (int c = 0; c < 8; c++)
                        acc[i][c] = __fmaf_rn(a[i], b[c], acc[i][c]);
            }
            __syncthreads();
        }
        // Reference epilogue: d = fl( fl(zz+see) - fl(2g) ).
        // j ascends within each slot -> strict < keeps lowest index,
        // reproducing argmin's first-occurrence tie rule on the buckets.
        #pragma unroll
        for (int c = 0; c < 8; c++) {
            int j = j0 + colb + c;
            float see = __ldg(&g_see[j]);
            #pragma unroll
            for (int i = 0; i < 8; i++) {
                float t1 = __fadd_rn(zzr[i], see);
                float d  = __fsub_rn(t1, __fadd_rn(acc[i][c], acc[i][c]));
                if (d < bestv[i]) { bestv[i] = d; besti[i] = j; }
            }
        }
    }

    // cross-thread reduction: 16 threads share each row octet
    __syncthreads();
    float* rv = &As[0][0];             // 2048 floats
    int*   ri = (int*)&Bs[0][0];       // 2048 ints
    const int tcol = wx * 8 + wc;      // 0..15
    #pragma unroll
    for (int i = 0; i < 8; i++) {
        int rowl = rowb + i;
        rv[rowl * 16 + tcol] = bestv[i];
        ri[rowl * 16 + tcol] = besti[i];
    }
    __syncthreads();
    if (tid < BM) {
        float bv = rv[tid * 16];
        int   bi = ri[tid * 16];
        #pragma unroll
        for (int q = 1; q < 16; q++) {
            float v  = rv[tid * 16 + q];
            int   ix = ri[tid * 16 + q];
            if (v < bv || (v == bv && ix < bi)) { bv = v; bi = ix; }
        }
        g_pval[h * M_ROWS + m0 + tid] = bv;
        g_pidx[h * M_ROWS + m0 + tid] = bi;
    }
}

// ============================================================
// Kernel 3: merge halves + histogram (half0 indices < half1 ->
// tie keeps half0 = lowest index, matching argmin)
// ============================================================
__global__ void merge_kernel() {
    int m = blockIdx.x * blockDim.x + threadIdx.x;
    if (m >= M_ROWS) return;
    float v0 = g_pval[m];          int i0 = g_pidx[m];
    float v1 = g_pval[M_ROWS + m]; int i1 = g_pidx[M_ROWS + m];
    int idx = (v1 < v0) ? i1 : i0;
    g_idx[m] = idx;
    atomicAdd(&g_counts[idx], 1);
}

// ============================================================
// Kernel 4: straight-through output (reference's exact two rounding
// ops -> bitwise output once idx matches) + fp64 loss accumulation
// ============================================================
__global__ void output_loss_kernel(const float* __restrict__ z,
                                   const float* __restrict__ emb,
                                   float* __restrict__ out) {
    int g = blockIdx.x * blockDim.x + threadIdx.x;   // < NET exactly
    int t = g & (TDIM - 1);
    int e = (g >> 9) & (EDIM - 1);
    int n = g >> 18;
    int m = n * TDIM + t;
    int j = g_idx[m];
    float zf = z[g];
    float zq = __ldg(emb + (size_t)j * EDIM + e);
    float dsub = __fsub_rn(zq, zf);      // fl(z_q - zf)
    out[g] = __fadd_rn(zf, dsub);        // fl(zf + fl(z_q - zf))
    float sq = __fmul_rn(dsub, dsub);

    __shared__ float red[256];
    red[threadIdx.x] = sq;
    __syncthreads();
    #pragma unroll
    for (int s = 128; s > 0; s >>= 1) {
        if (threadIdx.x < s) red[threadIdx.x] += red[threadIdx.x + s];
        __syncthreads();
    }
    if (threadIdx.x == 0) atomicAdd(&g_loss, (double)red[0]);
}

// ============================================================
// Kernel 5: perplexity + scalars
// ============================================================
__global__ void scalar_kernel(float* __restrict__ out) {
    __shared__ double red[256];
    double s = 0.0;
    for (int j = threadIdx.x; j < NE; j += 256) {
        float em   = (float)g_counts[j] / (float)M_ROWS;
        float term = em * logf(em + 1e-10f);
        s += (double)term;
    }
    red[threadIdx.x] = s;
    __syncthreads();
    #pragma unroll
    for (int st = 128; st > 0; st >>= 1) {
        if (threadIdx.x < st) red[threadIdx.x] += red[threadIdx.x + st];
        __syncthreads();
    }
    if (threadIdx.x == 0) {
        double mean = g_loss / (double)((size_t)M_ROWS * EDIM);
        out[NET]     = (float)(1.25 * mean);       // (1 + BETA) * mean
        out[NET + 1] = expf((float)(-red[0]));     // perplexity
    }
}

// ============================================================
extern "C" void kernel_launch(void* const* d_in, const int* in_sizes, int n_in,
                              void* d_out, int out_size) {
    (void)in_sizes; (void)n_in; (void)out_size;
    const float* z   = (const float*)d_in[0];   // [N, E, T] fp32
    const float* emb = (const float*)d_in[1];   // [n_e, E] fp32
    float* out = (float*)d_out;

    see_kernel<<<NE, 256>>>(emb);
    zz_kernel<<<M_ROWS, 256>>>(z);

    dim3 g2(2, 128);
    vq_argmin_kernel<<<g2, 256>>>(z, emb);

    merge_kernel<<<M_ROWS / 256, 256>>>();

    output_loss_kernel<<<NET / 256, 256>>>(z, emb, out);

    scalar_kernel<<<1, 256>>>(out);
}